// round 11
// baseline (speedup 1.0000x reference)
#include <cuda_runtime.h>
#include <cstdint>
#include <math_constants.h>

#define NSEG 128
#define P    512
#define D    64
#define KT   15
#define NC   8
#define TPB  512
#define NWB  (TPB/32)
#define NCH  4
#define SEG_BYTES   (P * D * 4)            // 131072
#define CHUNK_BYTES (SEG_BYTES / NCH)      // 32768

struct SmemLayout {
    float4             data[P * D / 4];    // 131072 B (16B aligned at offset 0)
    unsigned long long mbar[NCH];
    float4             scen[16];           // center row
    float              sdist[P];
    short              sidx[NC][16];
    int                sCnt[NC];
    int                sTaken[NC];
    float              sS[NC];
    float              sM[NC];
    float              sred[NWB];
    int                s_last;
};

__device__ float g_partials[NSEG];
__device__ int   g_ticket = 0;   // reset by last block each launch

__device__ __forceinline__ uint32_t smem_u32(const void* p) {
    return (uint32_t)__cvta_generic_to_shared(p);
}

__device__ __forceinline__ void mbar_wait(uint32_t mbar, uint32_t parity) {
    asm volatile(
        "{\n\t.reg .pred P1;\n\t"
        "WAIT_LOOP_%=:\n\t"
        "mbarrier.try_wait.parity.acquire.cta.shared::cta.b64 P1, [%0], %1, 0x989680;\n\t"
        "@P1 bra.uni WAIT_DONE_%=;\n\t"
        "bra.uni WAIT_LOOP_%=;\n\t"
        "WAIT_DONE_%=:\n\t}"
        :: "r"(mbar), "r"(parity) : "memory");
}

// ---------- Kernel P: L2 prefetch hint (free; keeps small M gain) ----------
__global__ __launch_bounds__(1024, 1)
void lmnn_prefetch_kernel(const float* __restrict__ outputs)
{
    const char* p = (const char*)outputs +
                    ((size_t)blockIdx.x * 1024 + threadIdx.x) * 128;
    asm volatile("prefetch.global.L2 [%0];" :: "l"(p));
}

// ---------- Kernel M: TMA + thread-per-point, shuffle-free distance ----------
__global__ __launch_bounds__(TPB, 1)
void lmnn_fused_kernel(const float* __restrict__ center,
                       const float* __restrict__ outputs,
                       const int*   __restrict__ labels,
                       float*       __restrict__ out)
{
    extern __shared__ char smem_raw[];
    SmemLayout* sm = (SmemLayout*)smem_raw;

    const int seg  = blockIdx.x;
    const int t    = threadIdx.x;
    const int w    = t >> 5;
    const int lane = t & 31;

    // ---- init mbarriers, then issue 4 bulk copies (TMA path) ----
    if (t == 0) {
        #pragma unroll
        for (int c = 0; c < NCH; ++c)
            asm volatile("mbarrier.init.shared.b64 [%0], %1;"
                         :: "r"(smem_u32(&sm->mbar[c])), "r"(1u));
        asm volatile("fence.proxy.async.shared::cta;" ::: "memory");
    }
    __syncthreads();
    if (t == 0) {
        const char* gsrc = (const char*)outputs + (size_t)seg * SEG_BYTES;
        #pragma unroll
        for (int c = 0; c < NCH; ++c) {
            const uint32_t mb = smem_u32(&sm->mbar[c]);
            asm volatile("mbarrier.arrive.expect_tx.shared.b64 _, [%0], %1;"
                         :: "r"(mb), "r"((uint32_t)CHUNK_BYTES) : "memory");
            asm volatile(
                "cp.async.bulk.shared::cluster.global.mbarrier::complete_tx::bytes "
                "[%0], [%1], %2, [%3];"
                :: "r"(smem_u32((char*)sm->data + c * CHUNK_BYTES)),
                   "l"(gsrc + c * CHUNK_BYTES),
                   "r"((uint32_t)CHUNK_BYTES), "r"(mb) : "memory");
        }
    }

    // ---- overlapped with TMA flight: center, own label, class scan ----
    if (t < 16) sm->scen[t] = __ldg(&((const float4*)(center + seg * D))[t]);
    const int lab_t = __ldg(&labels[seg * P + t]);

    // Warps 0..7: class scan. top_k over -dd has all finite entries equal
    // (dist broadcast along k), so jax tie-breaking selects the FIRST KT
    // same-class indices.
    if (w < NC) {
        int lab[16];
        #pragma unroll
        for (int u = 0; u < 16; ++u)
            lab[u] = __ldg(&labels[seg * P + u * 32 + lane]);
        int cnt = 0, taken = 0;
        #pragma unroll
        for (int u = 0; u < 16; ++u) {
            const bool m = (lab[u] == w);
            const unsigned mask = __ballot_sync(0xffffffffu, m);
            const int pc = __popc(mask);
            const int need = KT - taken;
            if (need > 0) {
                const int rank = __popc(mask & ((1u << lane) - 1u));
                if (m && rank < need)
                    sm->sidx[w][taken + rank] = (short)(u * 32 + lane);
                taken += (pc < need) ? pc : need;
            }
            cnt += pc;
        }
        if (lane == 0) { sm->sCnt[w] = cnt; sm->sTaken[w] = taken; }
    }
    __syncthreads();   // scen + scan results visible

    // ---- distance: thread t owns point t; wait only this warp's chunk ----
    // Point t = bytes [t*256, t*256+256) -> chunk t>>7 == w>>2.
    mbar_wait(smem_u32(&sm->mbar[w >> 2]), 0u);

    // 16 staggered LDS.128: idx=(k+t)&15 gives distinct bank-quads per
    // 8-lane phase -> conflict-free. Zero shuffles.
    const float4* __restrict__ row = sm->data + t * 16;
    float a0 = 0.f, a1 = 0.f, a2 = 0.f, a3 = 0.f;
    #pragma unroll
    for (int k = 0; k < 16; ++k) {
        const int idx = (k + t) & 15;
        const float4 x = row[idx];
        const float4 c = sm->scen[idx];
        const float dx = x.x - c.x;
        const float dy = x.y - c.y;
        const float dz = x.z - c.z;
        const float dw = x.w - c.w;
        a0 += dx * dx; a1 += dy * dy; a2 += dz * dz; a3 += dw * dw;
    }
    const float dist = (a0 + a1) + (a2 + a3);
    sm->sdist[t] = dist;
    __syncthreads();

    // ---- gather first-KT distances per class (warps 0..7) ----
    if (w < NC) {
        const int cnt   = sm->sCnt[w];
        const int taken = sm->sTaken[w];
        float d = (lane < KT)
                    ? ((lane < taken) ? sm->sdist[sm->sidx[w][lane]] : CUDART_INF_F)
                    : 0.0f;
        float S  = (lane < KT) ? d : 0.0f;
        float Mx = (lane < KT) ? d : -CUDART_INF_F;
        #pragma unroll
        for (int off = 16; off > 0; off >>= 1) {
            S += __shfl_xor_sync(0xffffffffu, S, off);
            Mx = fmaxf(Mx, __shfl_xor_sync(0xffffffffu, Mx, off));
        }
        if (lane == 0) {
            sm->sS[w] = (cnt > 0) ? S : 0.0f;
            sm->sM[w] = (cnt > 0) ? Mx : -CUDART_INF_F;
        }
    }
    __syncthreads();

    // ---- margin_seg = 1 + max over present classes ----
    float ms = -CUDART_INF_F;
    #pragma unroll
    for (int c = 0; c < NC; ++c)
        ms = fmaxf(ms, sm->sM[c]);
    ms += 1.0f;

    // ---- push term: in-register dist, own label; block shfl reduce ----
    float term = 0.0f;
    if (dist < ms)
        term = (float)(P - sm->sCnt[lab_t]) * fmaxf(1.0f + sm->sM[lab_t] - dist, 0.0f);
    #pragma unroll
    for (int off = 16; off > 0; off >>= 1)
        term += __shfl_xor_sync(0xffffffffu, term, off);
    if (lane == 0) sm->sred[w] = term;
    __syncthreads();

    // ---- per-segment partial + last-block finish ----
    if (t == 0) {
        float push = 0.0f;
        #pragma unroll
        for (int k = 0; k < NWB; ++k) push += sm->sred[k];
        float pull = 0.0f;
        #pragma unroll
        for (int c = 0; c < NC; ++c)
            pull += (float)sm->sCnt[c] * sm->sS[c];
        g_partials[seg] = pull + push;
        __threadfence();
        const int prev = atomicAdd(&g_ticket, 1);
        sm->s_last = (prev == NSEG - 1) ? 1 : 0;
    }
    __syncthreads();

    if (sm->s_last && w == 0) {
        __threadfence();
        const float a  = g_partials[lane];
        const float b  = g_partials[lane + 32];
        const float c2 = g_partials[lane + 64];
        const float d2 = g_partials[lane + 96];
        float vsum = (a + b) + (c2 + d2);
        #pragma unroll
        for (int off = 16; off > 0; off >>= 1)
            vsum += __shfl_xor_sync(0xffffffffu, vsum, off);
        if (lane == 0) {
            out[0] = vsum * (1.0f / (float)(NSEG * P));
            g_ticket = 0;   // reset for next graph replay
        }
    }
}

extern "C" void kernel_launch(void* const* d_in, const int* in_sizes, int n_in,
                              void* d_out, int out_size)
{
    const float* center  = (const float*)d_in[0];  // (128, 64)    f32
    const float* outputs = (const float*)d_in[1];  // (128,512,64) f32
    const int*   labels  = (const int*)d_in[2];    // (128, 512)   i32

    cudaFuncSetAttribute(lmnn_fused_kernel,
                         cudaFuncAttributeMaxDynamicSharedMemorySize,
                         (int)sizeof(SmemLayout));
    lmnn_prefetch_kernel<<<NSEG, 1024>>>(outputs);
    lmnn_fused_kernel<<<NSEG, TPB, sizeof(SmemLayout)>>>(
        center, outputs, labels, (float*)d_out);
}

// round 12
// speedup vs baseline: 1.0124x; 1.0124x over previous
#include <cuda_runtime.h>
#include <cstdint>
#include <math_constants.h>

#define NSEG 128
#define P    512
#define D    64
#define KT   15
#define NC   8
#define TPB  512
#define NWB  (TPB/32)
#define HALF4 4096            // float4s per half-segment

__device__ float g_partials[NSEG];
__device__ int   g_ticket = 0;   // reset by last finisher each launch

__device__ __forceinline__ uint32_t smem_u32(const void* p) {
    return (uint32_t)__cvta_generic_to_shared(p);
}

__global__ __launch_bounds__(TPB, 1) __cluster_dims__(2, 1, 1)
void lmnn_cluster_kernel(const float* __restrict__ center,
                         const float* __restrict__ outputs,
                         const int*   __restrict__ labels,
                         float*       __restrict__ out)
{
    __shared__ float sdist[P];
    __shared__ int   slab[P];
    __shared__ short sidx[NC][16];
    __shared__ int   sCnt[NC];
    __shared__ int   sTaken[NC];
    __shared__ float sS[NC];
    __shared__ float sM[NC];
    __shared__ float sred[NWB];
    __shared__ int   s_last;

    uint32_t rank;
    asm("mov.u32 %0, %%cluster_ctarank;" : "=r"(rank));
    const int seg  = blockIdx.x >> 1;
    const int t    = threadIdx.x;
    const int w    = t >> 5;
    const int lane = t & 31;
    const int col  = t & 15;

    // ---- front-batched loads of this CTA's 64KB half-segment ----
    // half-segment float4 index: t + 512*s (s<8); col = d-offset.
    const float4* __restrict__ out4 =
        (const float4*)(outputs + (size_t)seg * P * D) + rank * HALF4;
    float4 v[8];
    #pragma unroll
    for (int s = 0; s < 8; ++s)
        v[s] = __ldcs(&out4[t + TPB * s]);
    const float4 c4 = __ldg(&((const float4*)(center + seg * D))[col]);

    // ---- rank 0 only: class scan on labels, hidden under load flight ----
    // top_k over -dd has all finite entries equal (dist broadcast along k),
    // so jax tie-breaking selects the FIRST KT same-class indices.
    if (rank == 0 && w < NC) {
        int lab[16];
        #pragma unroll
        for (int u = 0; u < 16; ++u)
            lab[u] = __ldg(&labels[seg * P + u * 32 + lane]);
        if (w == 0) {
            #pragma unroll
            for (int u = 0; u < 16; ++u)
                slab[u * 32 + lane] = lab[u];
        }
        int cnt = 0, taken = 0;
        #pragma unroll
        for (int u = 0; u < 16; ++u) {
            const bool m = (lab[u] == w);
            const unsigned mask = __ballot_sync(0xffffffffu, m);
            const int pc = __popc(mask);
            const int need = KT - taken;
            if (need > 0) {
                const int rnk = __popc(mask & ((1u << lane) - 1u));
                if (m && rnk < need)
                    sidx[w][taken + rnk] = (short)(u * 32 + lane);
                taken += (pc < need) ? pc : need;
            }
            cnt += pc;
        }
        if (lane == 0) { sCnt[w] = cnt; sTaken[w] = taken; }
    }

    // ---- rank 1: resolve peer address of rank0's sdist once ----
    uint32_t peer_sdist = 0;
    if (rank == 1) {
        asm("mapa.shared::cluster.u32 %0, %1, 0;"
            : "=r"(peer_sdist) : "r"(smem_u32(sdist)));
    }

    // ---- distance compute: 16 lanes = one point ----
    #pragma unroll
    for (int s = 0; s < 8; ++s) {
        const int g = t + TPB * s;                 // local float4 idx 0..4095
        const float dx = v[s].x - c4.x;
        const float dy = v[s].y - c4.y;
        const float dz = v[s].z - c4.z;
        const float dw = v[s].w - c4.w;
        float part = dx * dx + dy * dy + dz * dz + dw * dw;
        part += __shfl_down_sync(0xffffffffu, part, 8);
        part += __shfl_down_sync(0xffffffffu, part, 4);
        part += __shfl_down_sync(0xffffffffu, part, 2);
        part += __shfl_down_sync(0xffffffffu, part, 1);
        if (col == 0) {
            const int pt = (int)(rank * (P / 2)) + (g >> 4);   // 0..511
            if (rank == 0) {
                sdist[pt] = part;
            } else {
                asm volatile("st.shared::cluster.f32 [%0], %1;"
                             :: "r"(peer_sdist + pt * 4), "f"(part) : "memory");
            }
        }
    }

    // ---- cluster barrier: rank1's DSMEM writes -> visible to rank0 ----
    asm volatile("barrier.cluster.arrive.aligned;" ::: "memory");
    asm volatile("barrier.cluster.wait.aligned;" ::: "memory");
    if (rank != 0) return;

    // ================== rank 0: full-segment phases ==================
    // ---- gather first-KT distances per class (warps 0..7) ----
    if (w < NC) {
        const int cnt   = sCnt[w];
        const int taken = sTaken[w];
        float d = (lane < KT)
                    ? ((lane < taken) ? sdist[sidx[w][lane]] : CUDART_INF_F)
                    : 0.0f;
        float S  = (lane < KT) ? d : 0.0f;
        float Mx = (lane < KT) ? d : -CUDART_INF_F;
        #pragma unroll
        for (int off = 16; off > 0; off >>= 1) {
            S += __shfl_xor_sync(0xffffffffu, S, off);
            Mx = fmaxf(Mx, __shfl_xor_sync(0xffffffffu, Mx, off));
        }
        if (lane == 0) {
            sS[w] = (cnt > 0) ? S : 0.0f;
            sM[w] = (cnt > 0) ? Mx : -CUDART_INF_F;
        }
    }
    __syncthreads();

    // ---- margin_seg = 1 + max over present classes ----
    float ms = -CUDART_INF_F;
    #pragma unroll
    for (int c = 0; c < NC; ++c)
        ms = fmaxf(ms, sM[c]);
    ms += 1.0f;

    // ---- push term: thread t owns point t ----
    float term = 0.0f;
    {
        const int   cj = slab[t];
        const float dv = sdist[t];
        if (dv < ms)
            term = (float)(P - sCnt[cj]) * fmaxf(1.0f + sM[cj] - dv, 0.0f);
    }
    #pragma unroll
    for (int off = 16; off > 0; off >>= 1)
        term += __shfl_xor_sync(0xffffffffu, term, off);
    if (lane == 0) sred[w] = term;
    __syncthreads();

    // ---- per-segment partial + last-finisher reduce ----
    if (t == 0) {
        float push = 0.0f;
        #pragma unroll
        for (int k = 0; k < NWB; ++k) push += sred[k];
        float pull = 0.0f;
        #pragma unroll
        for (int c = 0; c < NC; ++c)
            pull += (float)sCnt[c] * sS[c];
        g_partials[seg] = pull + push;
        __threadfence();
        const int prev = atomicAdd(&g_ticket, 1);
        s_last = (prev == NSEG - 1) ? 1 : 0;
    }
    __syncthreads();

    if (s_last && w == 0) {
        __threadfence();
        const float a  = g_partials[lane];
        const float b  = g_partials[lane + 32];
        const float c2 = g_partials[lane + 64];
        const float d2 = g_partials[lane + 96];
        float vsum = (a + b) + (c2 + d2);
        #pragma unroll
        for (int off = 16; off > 0; off >>= 1)
            vsum += __shfl_xor_sync(0xffffffffu, vsum, off);
        if (lane == 0) {
            out[0] = vsum * (1.0f / (float)(NSEG * P));
            g_ticket = 0;   // reset for next graph replay
        }
    }
}

extern "C" void kernel_launch(void* const* d_in, const int* in_sizes, int n_in,
                              void* d_out, int out_size)
{
    const float* center  = (const float*)d_in[0];  // (128, 64)    f32
    const float* outputs = (const float*)d_in[1];  // (128,512,64) f32
    const int*   labels  = (const int*)d_in[2];    // (128, 512)   i32

    lmnn_cluster_kernel<<<NSEG * 2, TPB>>>(center, outputs, labels, (float*)d_out);
}

// round 13
// speedup vs baseline: 1.0201x; 1.0075x over previous
#include <cuda_runtime.h>
#include <cstdint>
#include <math_constants.h>

#define NSEG 128
#define P    512
#define D    64
#define KT   15
#define NC   8
#define TPB  512
#define NCTA (NSEG/2)
#define NWB  (TPB/32)
#define NCH  4
#define SEG_BYTES   (P * D * 4)          // 131072
#define CHUNK_BYTES (SEG_BYTES / NCH)    // 32768

struct SmemLayout {
    float4             data[P * D / 4];  // seg B staging, 131072 B
    unsigned long long mbar[NCH];
    float4             scenB[16];
    float              sdistA[P];
    float              sdistB[P];
    int                slabA[P];
    short              sidx[2][NC][16];
    int                sCnt[2][NC];
    int                sTaken[2][NC];
    float              sS[2][NC];
    float              sM[2][NC];
    float              sred[NWB];
    int                s_last;
};

__device__ float g_part[NCTA];
__device__ int   g_ticket = 0;   // reset by last CTA each launch

__device__ __forceinline__ uint32_t smem_u32(const void* p) {
    return (uint32_t)__cvta_generic_to_shared(p);
}
__device__ __forceinline__ void mbar_wait(uint32_t mbar, uint32_t parity) {
    asm volatile(
        "{\n\t.reg .pred P1;\n\t"
        "WAIT_LOOP_%=:\n\t"
        "mbarrier.try_wait.parity.acquire.cta.shared::cta.b64 P1, [%0], %1, 0x989680;\n\t"
        "@P1 bra.uni WAIT_DONE_%=;\n\t"
        "bra.uni WAIT_LOOP_%=;\n\t"
        "WAIT_DONE_%=:\n\t}"
        :: "r"(mbar), "r"(parity) : "memory");
}

// class scan for one segment by one warp (class = cls, seg slot = slot).
// top_k over -dd has all finite entries equal (dist broadcast along k),
// so jax tie-breaking selects the FIRST KT same-class indices.
__device__ __forceinline__ void class_scan(SmemLayout* sm, const int* labels,
                                           int seg, int slot, int cls,
                                           int lane, bool publish)
{
    int lab[16];
    #pragma unroll
    for (int u = 0; u < 16; ++u)
        lab[u] = __ldg(&labels[seg * P + u * 32 + lane]);
    if (publish) {
        #pragma unroll
        for (int u = 0; u < 16; ++u)
            sm->slabA[u * 32 + lane] = lab[u];
    }
    int cnt = 0, taken = 0;
    #pragma unroll
    for (int u = 0; u < 16; ++u) {
        const bool m = (lab[u] == cls);
        const unsigned mask = __ballot_sync(0xffffffffu, m);
        const int pc = __popc(mask);
        const int need = KT - taken;
        if (need > 0) {
            const int rnk = __popc(mask & ((1u << lane) - 1u));
            if (m && rnk < need)
                sm->sidx[slot][cls][taken + rnk] = (short)(u * 32 + lane);
            taken += (pc < need) ? pc : need;
        }
        cnt += pc;
    }
    if (lane == 0) { sm->sCnt[slot][cls] = cnt; sm->sTaken[slot][cls] = taken; }
}

// gather + margin + push for one segment; returns pull+push (valid on t==0).
__device__ __forceinline__ float seg_phases(SmemLayout* sm, int slot,
                                            const float* sdist,
                                            int lab_t, float dist_t,
                                            int t, int w, int lane)
{
    if (w < NC) {
        const int cnt   = sm->sCnt[slot][w];
        const int taken = sm->sTaken[slot][w];
        float d = (lane < KT)
                    ? ((lane < taken) ? sdist[sm->sidx[slot][w][lane]] : CUDART_INF_F)
                    : 0.0f;
        float S  = (lane < KT) ? d : 0.0f;
        float Mx = (lane < KT) ? d : -CUDART_INF_F;
        #pragma unroll
        for (int off = 16; off > 0; off >>= 1) {
            S += __shfl_xor_sync(0xffffffffu, S, off);
            Mx = fmaxf(Mx, __shfl_xor_sync(0xffffffffu, Mx, off));
        }
        if (lane == 0) {
            sm->sS[slot][w] = (cnt > 0) ? S : 0.0f;
            sm->sM[slot][w] = (cnt > 0) ? Mx : -CUDART_INF_F;
        }
    }
    __syncthreads();

    float ms = -CUDART_INF_F;
    #pragma unroll
    for (int c = 0; c < NC; ++c)
        ms = fmaxf(ms, sm->sM[slot][c]);
    ms += 1.0f;

    float term = 0.0f;
    if (dist_t < ms)
        term = (float)(P - sm->sCnt[slot][lab_t]) *
               fmaxf(1.0f + sm->sM[slot][lab_t] - dist_t, 0.0f);
    #pragma unroll
    for (int off = 16; off > 0; off >>= 1)
        term += __shfl_xor_sync(0xffffffffu, term, off);
    if (lane == 0) sm->sred[w] = term;
    __syncthreads();

    float res = 0.0f;
    if (t == 0) {
        #pragma unroll
        for (int k = 0; k < NWB; ++k) res += sm->sred[k];
        #pragma unroll
        for (int c = 0; c < NC; ++c)
            res += (float)sm->sCnt[slot][c] * sm->sS[slot][c];
    }
    __syncthreads();   // sred/sM reusable afterwards
    return res;
}

__global__ __launch_bounds__(TPB, 1)
void lmnn_dual_kernel(const float* __restrict__ center,
                      const float* __restrict__ outputs,
                      const int*   __restrict__ labels,
                      float*       __restrict__ out)
{
    extern __shared__ char smem_raw[];
    SmemLayout* sm = (SmemLayout*)smem_raw;

    const int segA = blockIdx.x * 2;
    const int segB = segA + 1;
    const int t    = threadIdx.x;
    const int w    = t >> 5;
    const int lane = t & 31;
    const int col  = t & 15;

    // ---- t0: mbar init + TMA of segment B into smem (no regs, no LSU) ----
    if (t == 0) {
        #pragma unroll
        for (int c = 0; c < NCH; ++c)
            asm volatile("mbarrier.init.shared.b64 [%0], %1;"
                         :: "r"(smem_u32(&sm->mbar[c])), "r"(1u));
        asm volatile("fence.proxy.async.shared::cta;" ::: "memory");
        const char* gsrc = (const char*)outputs + (size_t)segB * SEG_BYTES;
        #pragma unroll
        for (int c = 0; c < NCH; ++c) {
            const uint32_t mb = smem_u32(&sm->mbar[c]);
            asm volatile("mbarrier.arrive.expect_tx.shared.b64 _, [%0], %1;"
                         :: "r"(mb), "r"((uint32_t)CHUNK_BYTES) : "memory");
            asm volatile(
                "cp.async.bulk.shared::cluster.global.mbarrier::complete_tx::bytes "
                "[%0], [%1], %2, [%3];"
                :: "r"(smem_u32((char*)sm->data + c * CHUNK_BYTES)),
                   "l"(gsrc + c * CHUNK_BYTES),
                   "r"((uint32_t)CHUNK_BYTES), "r"(mb) : "memory");
        }
    }

    // ---- segment A: front-batch 16 LDG.128 per thread (in flight now) ----
    const float4* __restrict__ outA = (const float4*)(outputs + (size_t)segA * P * D);
    float4 v[16];
    #pragma unroll
    for (int s = 0; s < 16; ++s)
        v[s] = __ldcs(&outA[t + TPB * s]);
    const float4 c4 = __ldg(&((const float4*)(center + segA * D))[col]);
    if (t < 16)
        sm->scenB[t] = __ldg(&((const float4*)(center + segB * D))[t]);
    const int labB_t = __ldg(&labels[segB * P + t]);

    // ---- both label scans under the load flight ----
    if (w < NC)
        class_scan(sm, labels, segA, 0, w, lane, w == 0);
    else
        class_scan(sm, labels, segB, 1, w - NC, lane, false);

    // ---- segment A distances: 16 lanes = one point ----
    #pragma unroll
    for (int s = 0; s < 16; ++s) {
        const int g = t + TPB * s;
        const float dx = v[s].x - c4.x;
        const float dy = v[s].y - c4.y;
        const float dz = v[s].z - c4.z;
        const float dw = v[s].w - c4.w;
        float part = dx * dx + dy * dy + dz * dz + dw * dw;
        part += __shfl_down_sync(0xffffffffu, part, 8);
        part += __shfl_down_sync(0xffffffffu, part, 4);
        part += __shfl_down_sync(0xffffffffu, part, 2);
        part += __shfl_down_sync(0xffffffffu, part, 1);
        if (col == 0) sm->sdistA[g >> 4] = part;
    }
    __syncthreads();   // sdistA + scans ready

    // ---- segment A phases ----
    const int   labA_t  = sm->slabA[t];
    const float distA_t = sm->sdistA[t];
    float total = seg_phases(sm, 0, sm->sdistA, labA_t, distA_t, t, w, lane);

    // ---- segment B: thread-per-point from smem (TMA landed long ago) ----
    mbar_wait(smem_u32(&sm->mbar[w >> 2]), 0u);   // chunk t>>7 == w>>2
    const float4* __restrict__ row = sm->data + t * 16;
    float a0 = 0.f, a1 = 0.f, a2 = 0.f, a3 = 0.f;
    #pragma unroll
    for (int k = 0; k < 16; ++k) {
        const int idx = (k + t) & 15;               // staggered: conflict-free
        const float4 x = row[idx];
        const float4 c = sm->scenB[idx];
        const float dx = x.x - c.x;
        const float dy = x.y - c.y;
        const float dz = x.z - c.z;
        const float dw = x.w - c.w;
        a0 += dx * dx; a1 += dy * dy; a2 += dz * dz; a3 += dw * dw;
    }
    const float distB_t = (a0 + a1) + (a2 + a3);
    sm->sdistB[t] = distB_t;
    __syncthreads();

    total += seg_phases(sm, 1, sm->sdistB, labB_t, distB_t, t, w, lane);

    // ---- per-CTA partial + last-CTA finish ----
    if (t == 0) {
        g_part[blockIdx.x] = total;
        __threadfence();
        const int prev = atomicAdd(&g_ticket, 1);
        sm->s_last = (prev == NCTA - 1) ? 1 : 0;
    }
    __syncthreads();

    if (sm->s_last && w == 0) {
        __threadfence();
        float vsum = g_part[lane] + g_part[lane + 32];
        #pragma unroll
        for (int off = 16; off > 0; off >>= 1)
            vsum += __shfl_xor_sync(0xffffffffu, vsum, off);
        if (lane == 0) {
            out[0] = vsum * (1.0f / (float)(NSEG * P));
            g_ticket = 0;   // reset for next graph replay
        }
    }
}

extern "C" void kernel_launch(void* const* d_in, const int* in_sizes, int n_in,
                              void* d_out, int out_size)
{
    const float* center  = (const float*)d_in[0];  // (128, 64)    f32
    const float* outputs = (const float*)d_in[1];  // (128,512,64) f32
    const int*   labels  = (const int*)d_in[2];    // (128, 512)   i32

    cudaFuncSetAttribute(lmnn_dual_kernel,
                         cudaFuncAttributeMaxDynamicSharedMemorySize,
                         (int)sizeof(SmemLayout));
    lmnn_dual_kernel<<<NCTA, TPB, sizeof(SmemLayout)>>>(
        center, outputs, labels, (float*)d_out);
}

// round 14
// speedup vs baseline: 1.1866x; 1.1633x over previous
#include <cuda_runtime.h>
#include <math_constants.h>

#define NSEG 128
#define P    512
#define D    64
#define KT   15
#define NC   8
#define NT   1024
#define NW   (NT/32)

__device__ float g_partials[NSEG];
__device__ int   g_ticket = 0;   // reset by last block each launch

// LDG.128 with an L2 256B prefetch window: each demand load also stages the
// adjacent 128B line in L2, halving demand-miss latency for the next load.
__device__ __forceinline__ float4 ldg128_l2_256(const float4* p)
{
    float4 v;
    asm volatile("ld.global.nc.L2::256B.v4.f32 {%0,%1,%2,%3}, [%4];"
                 : "=f"(v.x), "=f"(v.y), "=f"(v.z), "=f"(v.w)
                 : "l"(p));
    return v;
}

__global__ __launch_bounds__(NT, 1)
void lmnn_fused_kernel(const float* __restrict__ center,
                       const float* __restrict__ outputs,
                       const int*   __restrict__ labels,
                       float*       __restrict__ out)
{
    __shared__ float sdist[P];
    __shared__ int   slab[P];
    __shared__ short sidx[NC][16];
    __shared__ int   sCnt[NC];
    __shared__ int   sTaken[NC];
    __shared__ float sS[NC];
    __shared__ float sM[NC];
    __shared__ float sred[NW];
    __shared__ int   s_last;

    const int seg  = blockIdx.x;
    const int t    = threadIdx.x;
    const int w    = t >> 5;
    const int lane = t & 31;
    const int col  = t & 15;

    // ---- front-batched coalesced loads with L2::256B promotion ----
    // 8192 float4s/segment; thread t takes g = t + 1024*s. col = d-offset.
    const float4* __restrict__ out4 = (const float4*)(outputs + (size_t)seg * P * D);
    float4 v[8];
    #pragma unroll
    for (int s = 0; s < 8; ++s)
        v[s] = ldg128_l2_256(&out4[t + NT * s]);
    const float4 c4 = __ldg(&((const float4*)(center + seg * D))[col]);

    // ---- class scan on labels (warps 0..7), hidden under load flight ----
    // top_k over -dd has all finite entries equal (dist broadcast along k),
    // so jax tie-breaking selects the FIRST KT same-class indices.
    if (w < NC) {
        int lab[16];
        #pragma unroll
        for (int u = 0; u < 16; ++u)
            lab[u] = __ldg(&labels[seg * P + u * 32 + lane]);
        if (w == 0) {
            #pragma unroll
            for (int u = 0; u < 16; ++u)
                slab[u * 32 + lane] = lab[u];
        }
        int cnt = 0, taken = 0;
        #pragma unroll
        for (int u = 0; u < 16; ++u) {
            const bool m = (lab[u] == w);
            const unsigned mask = __ballot_sync(0xffffffffu, m);
            const int pc = __popc(mask);
            const int need = KT - taken;
            if (need > 0) {
                const int rank = __popc(mask & ((1u << lane) - 1u));
                if (m && rank < need)
                    sidx[w][taken + rank] = (short)(u * 32 + lane);
                taken += (pc < need) ? pc : need;
            }
            cnt += pc;
        }
        if (lane == 0) { sCnt[w] = cnt; sTaken[w] = taken; }
    }

    // ---- distance compute: 16 lanes = one point ----
    #pragma unroll
    for (int s = 0; s < 8; ++s) {
        const int g = t + NT * s;
        const float dx = v[s].x - c4.x;
        const float dy = v[s].y - c4.y;
        const float dz = v[s].z - c4.z;
        const float dw = v[s].w - c4.w;
        float part = dx * dx + dy * dy + dz * dz + dw * dw;
        part += __shfl_down_sync(0xffffffffu, part, 8);
        part += __shfl_down_sync(0xffffffffu, part, 4);
        part += __shfl_down_sync(0xffffffffu, part, 2);
        part += __shfl_down_sync(0xffffffffu, part, 1);
        if (col == 0) sdist[g >> 4] = part;
    }
    __syncthreads();

    // ---- gather first-KT distances per class (warps 0..7) ----
    if (w < NC) {
        const int cnt   = sCnt[w];
        const int taken = sTaken[w];
        float d = (lane < KT)
                    ? ((lane < taken) ? sdist[sidx[w][lane]] : CUDART_INF_F)
                    : 0.0f;
        float S  = (lane < KT) ? d : 0.0f;
        float Mx = (lane < KT) ? d : -CUDART_INF_F;
        #pragma unroll
        for (int off = 16; off > 0; off >>= 1) {
            S += __shfl_xor_sync(0xffffffffu, S, off);
            Mx = fmaxf(Mx, __shfl_xor_sync(0xffffffffu, Mx, off));
        }
        if (lane == 0) {
            sS[w] = (cnt > 0) ? S : 0.0f;
            sM[w] = (cnt > 0) ? Mx : -CUDART_INF_F;
        }
    }
    __syncthreads();

    // ---- margin_seg = 1 + max over present classes ----
    float ms = -CUDART_INF_F;
    #pragma unroll
    for (int c = 0; c < NC; ++c)
        ms = fmaxf(ms, sM[c]);
    ms += 1.0f;

    // ---- push term per point (first 512 threads) ----
    float term = 0.0f;
    if (t < P) {
        const int   cj = slab[t];
        const float dv = sdist[t];
        if (dv < ms)
            term = (float)(P - sCnt[cj]) * fmaxf(1.0f + sM[cj] - dv, 0.0f);
    }
    #pragma unroll
    for (int off = 16; off > 0; off >>= 1)
        term += __shfl_xor_sync(0xffffffffu, term, off);
    if (lane == 0) sred[w] = term;
    __syncthreads();

    // ---- per-segment partial + last-block finish ----
    if (t == 0) {
        float push = 0.0f;
        #pragma unroll
        for (int k = 0; k < NW; ++k) push += sred[k];
        float pull = 0.0f;
        #pragma unroll
        for (int c = 0; c < NC; ++c)
            pull += (float)sCnt[c] * sS[c];
        g_partials[seg] = pull + push;
        __threadfence();
        const int prev = atomicAdd(&g_ticket, 1);
        s_last = (prev == NSEG - 1) ? 1 : 0;
    }
    __syncthreads();

    if (s_last && w == 0) {
        __threadfence();
        const float a  = g_partials[lane];
        const float b  = g_partials[lane + 32];
        const float c2 = g_partials[lane + 64];
        const float d2 = g_partials[lane + 96];
        float vsum = (a + b) + (c2 + d2);
        #pragma unroll
        for (int off = 16; off > 0; off >>= 1)
            vsum += __shfl_xor_sync(0xffffffffu, vsum, off);
        if (lane == 0) {
            out[0] = vsum * (1.0f / (float)(NSEG * P));
            g_ticket = 0;   // reset for next graph replay
        }
    }
}

extern "C" void kernel_launch(void* const* d_in, const int* in_sizes, int n_in,
                              void* d_out, int out_size)
{
    const float* center  = (const float*)d_in[0];  // (128, 64)    f32
    const float* outputs = (const float*)d_in[1];  // (128,512,64) f32
    const int*   labels  = (const int*)d_in[2];    // (128, 512)   i32

    lmnn_fused_kernel<<<NSEG, NT>>>(center, outputs, labels, (float*)d_out);
}

// round 15
// speedup vs baseline: 1.2149x; 1.0239x over previous
#include <cuda_runtime.h>
#include <math_constants.h>

#define NSEG 128
#define P    512
#define D    64
#define KT   15
#define NC   8
#define NT   1024
#define NW   (NT/32)

__device__ float g_partials[NSEG];
__device__ int   g_ticket = 0;   // reset by last block each launch

// L2-only load (bypass L1D): the one datapath not yet tested.
__device__ __forceinline__ float4 ldg128_cg(const float4* p)
{
    float4 v;
    asm volatile("ld.global.cg.v4.f32 {%0,%1,%2,%3}, [%4];"
                 : "=f"(v.x), "=f"(v.y), "=f"(v.z), "=f"(v.w)
                 : "l"(p));
    return v;
}

// ---------- Kernel P: L2 prefetch hint (measured free / slightly +) ----------
__global__ __launch_bounds__(NT, 1)
void lmnn_prefetch_kernel(const float* __restrict__ outputs)
{
    const char* p = (const char*)outputs +
                    ((size_t)blockIdx.x * NT + threadIdx.x) * 128;
    asm volatile("prefetch.global.L2 [%0];" :: "l"(p));
}

// ---------- Kernel M: champion skeleton, loads switched to .cg ----------
__global__ __launch_bounds__(NT, 1)
void lmnn_fused_kernel(const float* __restrict__ center,
                       const float* __restrict__ outputs,
                       const int*   __restrict__ labels,
                       float*       __restrict__ out)
{
    __shared__ float sdist[P];
    __shared__ int   slab[P];
    __shared__ short sidx[NC][16];
    __shared__ int   sCnt[NC];
    __shared__ int   sTaken[NC];
    __shared__ float sS[NC];
    __shared__ float sM[NC];
    __shared__ float sred[NW];
    __shared__ int   s_last;

    const int seg  = blockIdx.x;
    const int t    = threadIdx.x;
    const int w    = t >> 5;
    const int lane = t & 31;
    const int col  = t & 15;

    // ---- front-batched coalesced loads, L2-only path ----
    // 8192 float4s/segment; thread t takes g = t + 1024*s. col = d-offset.
    const float4* __restrict__ out4 = (const float4*)(outputs + (size_t)seg * P * D);
    float4 v[8];
    #pragma unroll
    for (int s = 0; s < 8; ++s)
        v[s] = ldg128_cg(&out4[t + NT * s]);
    const float4 c4 = __ldg(&((const float4*)(center + seg * D))[col]);

    // ---- class scan on labels (warps 0..7), hidden under load flight ----
    // top_k over -dd has all finite entries equal (dist broadcast along k),
    // so jax tie-breaking selects the FIRST KT same-class indices.
    if (w < NC) {
        int lab[16];
        #pragma unroll
        for (int u = 0; u < 16; ++u)
            lab[u] = __ldg(&labels[seg * P + u * 32 + lane]);
        if (w == 0) {
            #pragma unroll
            for (int u = 0; u < 16; ++u)
                slab[u * 32 + lane] = lab[u];
        }
        int cnt = 0, taken = 0;
        #pragma unroll
        for (int u = 0; u < 16; ++u) {
            const bool m = (lab[u] == w);
            const unsigned mask = __ballot_sync(0xffffffffu, m);
            const int pc = __popc(mask);
            const int need = KT - taken;
            if (need > 0) {
                const int rank = __popc(mask & ((1u << lane) - 1u));
                if (m && rank < need)
                    sidx[w][taken + rank] = (short)(u * 32 + lane);
                taken += (pc < need) ? pc : need;
            }
            cnt += pc;
        }
        if (lane == 0) { sCnt[w] = cnt; sTaken[w] = taken; }
    }

    // ---- distance compute: 16 lanes = one point ----
    #pragma unroll
    for (int s = 0; s < 8; ++s) {
        const int g = t + NT * s;
        const float dx = v[s].x - c4.x;
        const float dy = v[s].y - c4.y;
        const float dz = v[s].z - c4.z;
        const float dw = v[s].w - c4.w;
        float part = dx * dx + dy * dy + dz * dz + dw * dw;
        part += __shfl_down_sync(0xffffffffu, part, 8);
        part += __shfl_down_sync(0xffffffffu, part, 4);
        part += __shfl_down_sync(0xffffffffu, part, 2);
        part += __shfl_down_sync(0xffffffffu, part, 1);
        if (col == 0) sdist[g >> 4] = part;
    }
    __syncthreads();

    // ---- gather first-KT distances per class (warps 0..7) ----
    if (w < NC) {
        const int cnt   = sCnt[w];
        const int taken = sTaken[w];
        float d = (lane < KT)
                    ? ((lane < taken) ? sdist[sidx[w][lane]] : CUDART_INF_F)
                    : 0.0f;
        float S  = (lane < KT) ? d : 0.0f;
        float Mx = (lane < KT) ? d : -CUDART_INF_F;
        #pragma unroll
        for (int off = 16; off > 0; off >>= 1) {
            S += __shfl_xor_sync(0xffffffffu, S, off);
            Mx = fmaxf(Mx, __shfl_xor_sync(0xffffffffu, Mx, off));
        }
        if (lane == 0) {
            sS[w] = (cnt > 0) ? S : 0.0f;
            sM[w] = (cnt > 0) ? Mx : -CUDART_INF_F;
        }
    }
    __syncthreads();

    // ---- margin_seg = 1 + max over present classes ----
    float ms = -CUDART_INF_F;
    #pragma unroll
    for (int c = 0; c < NC; ++c)
        ms = fmaxf(ms, sM[c]);
    ms += 1.0f;

    // ---- push term per point (first 512 threads) ----
    float term = 0.0f;
    if (t < P) {
        const int   cj = slab[t];
        const float dv = sdist[t];
        if (dv < ms)
            term = (float)(P - sCnt[cj]) * fmaxf(1.0f + sM[cj] - dv, 0.0f);
    }
    #pragma unroll
    for (int off = 16; off > 0; off >>= 1)
        term += __shfl_xor_sync(0xffffffffu, term, off);
    if (lane == 0) sred[w] = term;
    __syncthreads();

    // ---- per-segment partial + last-block finish ----
    if (t == 0) {
        float push = 0.0f;
        #pragma unroll
        for (int k = 0; k < NW; ++k) push += sred[k];
        float pull = 0.0f;
        #pragma unroll
        for (int c = 0; c < NC; ++c)
            pull += (float)sCnt[c] * sS[c];
        g_partials[seg] = pull + push;
        __threadfence();
        const int prev = atomicAdd(&g_ticket, 1);
        s_last = (prev == NSEG - 1) ? 1 : 0;
    }
    __syncthreads();

    if (s_last && w == 0) {
        __threadfence();
        const float a  = g_partials[lane];
        const float b  = g_partials[lane + 32];
        const float c2 = g_partials[lane + 64];
        const float d2 = g_partials[lane + 96];
        float vsum = (a + b) + (c2 + d2);
        #pragma unroll
        for (int off = 16; off > 0; off >>= 1)
            vsum += __shfl_xor_sync(0xffffffffu, vsum, off);
        if (lane == 0) {
            out[0] = vsum * (1.0f / (float)(NSEG * P));
            g_ticket = 0;   // reset for next graph replay
        }
    }
}

extern "C" void kernel_launch(void* const* d_in, const int* in_sizes, int n_in,
                              void* d_out, int out_size)
{
    const float* center  = (const float*)d_in[0];  // (128, 64)    f32
    const float* outputs = (const float*)d_in[1];  // (128,512,64) f32
    const int*   labels  = (const int*)d_in[2];    // (128, 512)   i32

    lmnn_prefetch_kernel<<<NSEG, NT>>>(outputs);
    lmnn_fused_kernel<<<NSEG, NT>>>(center, outputs, labels, (float*)d_out);
}

// round 16
// speedup vs baseline: 1.3658x; 1.1242x over previous
#include <cuda_runtime.h>
#include <math_constants.h>

#define NSEG 128
#define P    512
#define D    64
#define KT   15
#define NC   8
#define NT   1024
#define NW   (NT/32)

__device__ float g_accum  = 0.0f;   // running sum; reset by last CTA
__device__ int   g_ticket = 0;      // reset by last CTA

__global__ __launch_bounds__(NT, 1)
void lmnn_fused_kernel(const float* __restrict__ center,
                       const float* __restrict__ outputs,
                       const int*   __restrict__ labels,
                       float*       __restrict__ out)
{
    __shared__ float sdist[P];
    __shared__ int   slab[P];
    __shared__ short sidx[NC][16];
    __shared__ int   sCnt[NC];
    __shared__ int   sTaken[NC];
    __shared__ float sS[NC];
    __shared__ float sM[NC];
    __shared__ float sred[NW];

    const int seg  = blockIdx.x;
    const int t    = threadIdx.x;
    const int w    = t >> 5;
    const int lane = t & 31;
    const int col  = t & 15;

    // ---- front-batched coalesced streaming loads ----
    // 8192 float4s/segment; thread t takes g = t + 1024*s. col = d-offset.
    const float4* __restrict__ out4 = (const float4*)(outputs + (size_t)seg * P * D);
    float4 v[8];
    #pragma unroll
    for (int s = 0; s < 8; ++s)
        v[s] = __ldcs(&out4[t + NT * s]);
    const float4 c4 = __ldg(&((const float4*)(center + seg * D))[col]);

    // ---- class scan on labels (warps 0..7), hidden under load flight ----
    // top_k over -dd has all finite entries equal (dist broadcast along k),
    // so jax tie-breaking selects the FIRST KT same-class indices.
    if (w < NC) {
        int lab[16];
        #pragma unroll
        for (int u = 0; u < 16; ++u)
            lab[u] = __ldg(&labels[seg * P + u * 32 + lane]);
        if (w == 0) {
            #pragma unroll
            for (int u = 0; u < 16; ++u)
                slab[u * 32 + lane] = lab[u];
        }
        int cnt = 0, taken = 0;
        #pragma unroll
        for (int u = 0; u < 16; ++u) {
            const bool m = (lab[u] == w);
            const unsigned mask = __ballot_sync(0xffffffffu, m);
            const int pc = __popc(mask);
            const int need = KT - taken;
            if (need > 0) {
                const int rank = __popc(mask & ((1u << lane) - 1u));
                if (m && rank < need)
                    sidx[w][taken + rank] = (short)(u * 32 + lane);
                taken += (pc < need) ? pc : need;
            }
            cnt += pc;
        }
        if (lane == 0) { sCnt[w] = cnt; sTaken[w] = taken; }
    }

    // ---- distance compute: 16 lanes = one point ----
    #pragma unroll
    for (int s = 0; s < 8; ++s) {
        const int g = t + NT * s;
        const float dx = v[s].x - c4.x;
        const float dy = v[s].y - c4.y;
        const float dz = v[s].z - c4.z;
        const float dw = v[s].w - c4.w;
        float part = dx * dx + dy * dy + dz * dz + dw * dw;
        part += __shfl_down_sync(0xffffffffu, part, 8);
        part += __shfl_down_sync(0xffffffffu, part, 4);
        part += __shfl_down_sync(0xffffffffu, part, 2);
        part += __shfl_down_sync(0xffffffffu, part, 1);
        if (col == 0) sdist[g >> 4] = part;
    }
    __syncthreads();

    // ---- gather first-KT distances per class (warps 0..7) ----
    if (w < NC) {
        const int cnt   = sCnt[w];
        const int taken = sTaken[w];
        float d = (lane < KT)
                    ? ((lane < taken) ? sdist[sidx[w][lane]] : CUDART_INF_F)
                    : 0.0f;
        float S  = (lane < KT) ? d : 0.0f;
        float Mx = (lane < KT) ? d : -CUDART_INF_F;
        #pragma unroll
        for (int off = 16; off > 0; off >>= 1) {
            S += __shfl_xor_sync(0xffffffffu, S, off);
            Mx = fmaxf(Mx, __shfl_xor_sync(0xffffffffu, Mx, off));
        }
        if (lane == 0) {
            sS[w] = (cnt > 0) ? S : 0.0f;
            sM[w] = (cnt > 0) ? Mx : -CUDART_INF_F;
        }
    }
    __syncthreads();

    // ---- margin_seg = 1 + max over present classes ----
    float ms = -CUDART_INF_F;
    #pragma unroll
    for (int c = 0; c < NC; ++c)
        ms = fmaxf(ms, sM[c]);
    ms += 1.0f;

    // ---- push term per point (first 512 threads) ----
    float term = 0.0f;
    if (t < P) {
        const int   cj = slab[t];
        const float dv = sdist[t];
        if (dv < ms)
            term = (float)(P - sCnt[cj]) * fmaxf(1.0f + sM[cj] - dv, 0.0f);
    }
    #pragma unroll
    for (int off = 16; off > 0; off >>= 1)
        term += __shfl_xor_sync(0xffffffffu, term, off);
    if (lane == 0) sred[w] = term;
    __syncthreads();

    // ---- tail: accumulate into device scalar; last CTA emits result ----
    if (t == 0) {
        float push = 0.0f;
        #pragma unroll
        for (int k = 0; k < NW; ++k) push += sred[k];
        float pull = 0.0f;
        #pragma unroll
        for (int c = 0; c < NC; ++c)
            pull += (float)sCnt[c] * sS[c];

        atomicAdd(&g_accum, pull + push);      // fire-and-forget REDG
        __threadfence();
        const int prev = atomicAdd(&g_ticket, 1);
        if (prev == NSEG - 1) {
            // All adds precede their ticket increments; last ticket => sum
            // complete. Exchange reads the total AND resets for next replay.
            const float total = atomicExch(&g_accum, 0.0f);
            out[0] = total * (1.0f / (float)(NSEG * P));
            g_ticket = 0;                      // reset for next graph replay
        }
    }
}

extern "C" void kernel_launch(void* const* d_in, const int* in_sizes, int n_in,
                              void* d_out, int out_size)
{
    const float* center  = (const float*)d_in[0];  // (128, 64)    f32
    const float* outputs = (const float*)d_in[1];  // (128,512,64) f32
    const int*   labels  = (const int*)d_in[2];    // (128, 512)   i32

    lmnn_fused_kernel<<<NSEG, NT>>>(center, outputs, labels, (float*)d_out);
}